// round 9
// baseline (speedup 1.0000x reference)
#include <cuda_runtime.h>
#include <cuda_bf16.h>

// CorrelationLayer: out[b,d,h,w] = (1/sqrt(C)) * sum_c x1[b,c,h,w] * x2pad[b,c,h+di,w+dj]
// 80 displacements. B=8, C=128, H=128, W=192, fp32.
// v9: v8 (persistent + ticket + continuous pipeline) with OOB halo zeroing
//     only at tile-boundary issues (st==0 / st==15) instead of every stage.

#define CC   128
#define HH   128
#define WW   192
#define PW   64
#define PH   2
#define CHS  8
#define TX   16
#define NDI  9
#define NTHREADS 288
#define NSTAGES  16
#define HALO_H   10
#define HALO_W   72
#define S1_FLT   (CHS * PH * PW)          // 1024
#define S2_FLT   (CHS * HALO_H * HALO_W)  // 5760
#define X2_SLOTS 5
#define NTILES   (3 * 64 * 8)             // 1536
#define NBLK     444                      // 148 SMs * 3 blocks
#define GSTEP    ((unsigned)(CHS * HH * WW * 4))

__device__ unsigned g_ticket;
__global__ void reset_ticket() { g_ticket = NBLK; }

__device__ __forceinline__ unsigned smem_u32(const void* p) {
    return (unsigned)__cvta_generic_to_shared(p);
}
__device__ __forceinline__ void cp16(unsigned dst, const char* base, unsigned off) {
    asm volatile("cp.async.cg.shared.global [%0], [%1], 16;\n"
                 :: "r"(dst), "l"(base + off));
}
__device__ __forceinline__ void sts_zero16(unsigned dst) {
    asm volatile("st.shared.v4.u32 [%0], {%1,%1,%1,%1};\n" :: "r"(dst), "r"(0u));
}
__device__ __forceinline__ void cp_commit() {
    asm volatile("cp.async.commit_group;\n" ::: "memory");
}
template <int N> __device__ __forceinline__ void cp_wait() {
    asm volatile("cp.async.wait_group %0;\n" :: "n"(N) : "memory");
}

__global__ __launch_bounds__(NTHREADS, 3)
void corr_kernel(const float* __restrict__ x1,
                 const float* __restrict__ x2,
                 float* __restrict__ out)
{
    __shared__ __align__(16) float s1[2][CHS][PH][PW];
    __shared__ __align__(16) float s2[2][CHS][HALO_H][HALO_W];
    __shared__ unsigned s_next;

    const int tid = threadIdx.x;
    const int tx  = tid & 15;
    const int hs  = (tid >> 4) & 1;
    const int w   = tid >> 5;
    const int pz  = hs;                      // diagonal pairing
    const int diI = hs ? (w + 8) % 9 : w;
    const int r2  = pz + diI;

    const char* base1 = (const char*)x1;
    const char* base2 = (const char*)x2;

    // ---- fixed smem slot addresses (buffer 0) ----
    const bool has1 = (tid < 256);
    unsigned s1off = 0;
    if (has1) {
        int ch = tid >> 5, r = (tid >> 4) & 1, c4 = tid & 15;
        s1off = smem_u32(&s1[0][ch][r][4 * c4]);
    }
    unsigned s2off[X2_SLOTS];
    #pragma unroll
    for (int sl = 0; sl < X2_SLOTS; sl++) {
        int i   = tid + NTHREADS * sl;
        int ch  = i / 180;
        int rem = i - ch * 180;
        int rr  = rem / 18;
        int c4  = rem - rr * 18;
        s2off[sl] = smem_u32(&s2[0][ch][rr][4 * c4]);
    }

    unsigned g1off = 0;
    unsigned g2off[X2_SLOTS];
    bool     pr[X2_SLOTS];

    auto setup = [&](unsigned t) {
        unsigned wx = t % 3u;
        unsigned q  = t / 3u;
        int w0 = (int)wx * PW;
        int h0 = (int)(q & 63u) * PH;
        int b  = (int)(q >> 6);
        if (has1) {
            int ch = tid >> 5, r = (tid >> 4) & 1, c4 = tid & 15;
            g1off = (unsigned)((((b * CC + ch) * HH + h0 + r) * WW + w0 + 4 * c4) * 4);
        }
        #pragma unroll
        for (int sl = 0; sl < X2_SLOTS; sl++) {
            int i   = tid + NTHREADS * sl;
            int ch  = i / 180;
            int rem = i - ch * 180;
            int rr  = rem / 18;
            int c4  = rem - rr * 18;
            int hr  = h0 - 4 + rr;
            int wc  = w0 - 4 + 4 * c4;
            pr[sl] = (hr >= 0) && (hr < HH) && (wc >= 0) && (wc < WW);
            int hrc = pr[sl] ? hr : 0;
            int wcc = pr[sl] ? wc : 0;
            g2off[sl] = (unsigned)((((b * CC + ch) * HH + hrc) * WW + wcc) * 4);
        }
    };

    // zero_oob: write zeros to OOB slots (needed only when the predicate
    // pattern for this buffer may have changed, i.e. at tile-boundary issues).
    auto issue = [&](int buf, bool zero_oob) {
        const unsigned b1 = (unsigned)buf * (S1_FLT * 4);
        const unsigned b2 = (unsigned)buf * (S2_FLT * 4);
        if (has1) cp16(s1off + b1, base1, g1off);
        #pragma unroll
        for (int sl = 0; sl < X2_SLOTS; sl++) {
            if (pr[sl])        cp16(s2off[sl] + b2, base2, g2off[sl]);
            else if (zero_oob) sts_zero16(s2off[sl] + b2);
        }
        cp_commit();
    };

    float acc[9][4];
    #pragma unroll
    for (int j = 0; j < 9; j++)
        #pragma unroll
        for (int k = 0; k < 4; k++) acc[j][k] = 0.0f;

    unsigned t = blockIdx.x;
    setup(t);
    issue(0, true);
    unsigned gs = 0;

    const float scale = 0.08838834764831845f;   // 1/sqrt(128)

    for (;;) {
        unsigned q  = t / 3u;
        unsigned obase = (((q >> 6) * 80u) * HH + ((q & 63u) * PH + pz)) * WW
                       + (t % 3u) * PW + 4 * tx;
        unsigned tnext = NTILES;

        #pragma unroll 1
        for (int st = 0; st < NSTAGES; st++, gs++) {
            const int bb = (int)(gs & 1u);
            cp_wait<0>();
            __syncthreads();

            if (st == 0) {
                if (tid == 0) s_next = atomicAdd(&g_ticket, 1u);
            }
            if (st < NSTAGES - 1) {
                g1off += GSTEP;
                #pragma unroll
                for (int sl = 0; sl < X2_SLOTS; sl++) g2off[sl] += GSTEP;
                // st==0 issues stage 1: buffer's OOB pattern is from the
                // previous tile -> re-zero. Stages 1..14: pattern unchanged.
                issue(bb ^ 1, st == 0);
            } else {
                tnext = s_next;
                if (tnext < NTILES) { setup(tnext); issue(bb ^ 1, true); }
            }

            const float* p1 = &s1[bb][0][pz][4 * tx];
            const float* p2 = &s2[bb][0][r2][4 * tx];
            #pragma unroll
            for (int ch = 0; ch < CHS; ch++) {
                float4 a4 = *(const float4*)(p1 + ch * (PH * PW));
                float4 t0 = *(const float4*)(p2 + ch * (HALO_H * HALO_W));
                float4 t1 = *(const float4*)(p2 + ch * (HALO_H * HALO_W) + 4);
                float4 t2 = *(const float4*)(p2 + ch * (HALO_H * HALO_W) + 8);
                float a[4]  = {a4.x, a4.y, a4.z, a4.w};
                float v[12] = {t0.x, t0.y, t0.z, t0.w,
                               t1.x, t1.y, t1.z, t1.w,
                               t2.x, t2.y, t2.z, t2.w};
                #pragma unroll
                for (int j = 0; j < 9; j++)
                    #pragma unroll
                    for (int k = 0; k < 4; k++)
                        acc[j][k] = fmaf(a[k], v[j + k], acc[j][k]);
            }
        }

        // ---- epilogue (overlaps the already-issued next-tile loads) ----
        #pragma unroll
        for (int j = 0; j < 9; j++) {
            int lin = diI * 9 + j;
            if (lin == 40) continue;               // (0,0) displacement
            int d = lin - (lin > 40 ? 1 : 0);
            float4 o;
            o.x = acc[j][0] * scale;
            o.y = acc[j][1] * scale;
            o.z = acc[j][2] * scale;
            o.w = acc[j][3] * scale;
            *(float4*)&out[obase + (unsigned)d * (HH * WW)] = o;
        }

        if (tnext >= NTILES) break;
        #pragma unroll
        for (int j = 0; j < 9; j++)
            #pragma unroll
            for (int k = 0; k < 4; k++) acc[j][k] = 0.0f;
        t = tnext;
    }
}

extern "C" void kernel_launch(void* const* d_in, const int* in_sizes, int n_in,
                              void* d_out, int out_size)
{
    const float* x1 = (const float*)d_in[0];
    const float* x2 = (const float*)d_in[1];
    float* out = (float*)d_out;

    reset_ticket<<<1, 1>>>();
    corr_kernel<<<NBLK, NTHREADS>>>(x1, x2, out);
}

// round 10
// speedup vs baseline: 1.0232x; 1.0232x over previous
#include <cuda_runtime.h>
#include <cuda_bf16.h>

// CorrelationLayer: out[b,d,h,w] = (1/sqrt(C)) * sum_c x1[b,c,h,w] * x2pad[b,c,h+di,w+dj]
// 80 displacements. B=8, C=128, H=128, W=192, fp32.
// v10: 6 px/thread (PW=96, TX=16, PH=2): 54 acc regs, 1.48 B/FMA LDS traffic
//      (vs 1.78), affine smem slot addressing, persistent ticket scheduler,
//      continuous cp.async pipeline.

#define CC   128
#define HH   128
#define WW   192
#define PW   96
#define PH   2
#define CHS  8
#define TX   16
#define NDI  9
#define NTHREADS 288
#define NSTAGES  16
#define HALO_H   10
#define HALO_W   104
#define S1_FLT   (CHS * PH * PW)          // 1536
#define S2_FLT   (CHS * HALO_H * HALO_W)  // 8320
#define S1_F4    (S1_FLT / 4)             // 384
#define S2_F4    (S2_FLT / 4)             // 2080
#define NTILES   (2 * 64 * 8)             // 1024
#define NBLK     296                      // 148 SMs * 2 blocks
#define GSTEP    ((unsigned)(CHS * HH * WW * 4))   // 786432 B
#define S1_BUFB  (S1_FLT * 4)             // 6144 B per s1 buffer
#define S2_BUFB  (S2_FLT * 4)             // 33280 B per s2 buffer
#define SLOT_B   (NTHREADS * 16)          // 4608 B per slot stride

__device__ unsigned g_ticket;
__global__ void reset_ticket() { g_ticket = NBLK; }

__device__ __forceinline__ unsigned smem_u32(const void* p) {
    return (unsigned)__cvta_generic_to_shared(p);
}
__device__ __forceinline__ void cp16(unsigned dst, const char* base, unsigned off) {
    asm volatile("cp.async.cg.shared.global [%0], [%1], 16;\n"
                 :: "r"(dst), "l"(base + off));
}
__device__ __forceinline__ void sts_zero16(unsigned dst) {
    asm volatile("st.shared.v4.u32 [%0], {%1,%1,%1,%1};\n" :: "r"(dst), "r"(0u));
}
__device__ __forceinline__ void cp_commit() {
    asm volatile("cp.async.commit_group;\n" ::: "memory");
}
template <int N> __device__ __forceinline__ void cp_wait() {
    asm volatile("cp.async.wait_group %0;\n" :: "n"(N) : "memory");
}

__global__ __launch_bounds__(NTHREADS, 2)
void corr_kernel(const float* __restrict__ x1,
                 const float* __restrict__ x2,
                 float* __restrict__ out)
{
    __shared__ __align__(16) float s1[2][CHS][PH][PW];          // 12 KB
    __shared__ __align__(16) float s2[2][CHS][HALO_H][HALO_W];  // 65 KB
    __shared__ unsigned s_next;

    const int tid = threadIdx.x;
    const int tx  = tid & 15;
    const int hs  = (tid >> 4) & 1;
    const int w   = tid >> 5;
    const int pz  = hs;                       // diagonal pairing
    const int diI = hs ? (w + 8) % 9 : w;
    const int r2  = pz + diI;

    const char* base1 = (const char*)x1;
    const char* base2 = (const char*)x2;

    // Affine smem slot addresses: slot f4 index i = tid + 288*sl -> byte 16*i.
    const unsigned s1base = smem_u32(&s1[0][0][0][0]) + 16u * tid;
    const unsigned s2base = smem_u32(&s2[0][0][0][0]) + 16u * tid;

    unsigned g1off[2];
    unsigned g2off[8];
    bool     pr[8];

    auto setup = [&](unsigned t) {
        int w0 = (int)(t & 1u) * PW;
        unsigned q = t >> 1;
        int h0 = (int)(q & 63u) * PH;
        int b  = (int)(q >> 6);
        #pragma unroll
        for (int sl = 0; sl < 2; sl++) {
            int i  = tid + NTHREADS * sl;
            int ii = (i < S1_F4) ? i : 0;
            int ch = ii / 48, rem = ii - ch * 48;
            int rr = rem / 24, c4 = rem - rr * 24;
            g1off[sl] = (unsigned)((((b * CC + ch) * HH + h0 + rr) * WW + w0 + 4 * c4) * 4);
        }
        #pragma unroll
        for (int sl = 0; sl < 8; sl++) {
            int i  = tid + NTHREADS * sl;
            int ii = (i < S2_F4) ? i : 0;
            int ch  = ii / 260, rem = ii - ch * 260;
            int rr  = rem / 26,  c4 = rem - rr * 26;
            int hr  = h0 - 4 + rr;
            int wc  = w0 - 4 + 4 * c4;
            pr[sl] = (i < S2_F4) && (hr >= 0) && (hr < HH) && (wc >= 0) && (wc < WW);
            int hrc = pr[sl] ? hr : 0;
            int wcc = pr[sl] ? wc : 0;
            g2off[sl] = (unsigned)((((b * CC + ch) * HH + hrc) * WW + wcc) * 4);
        }
    };

    auto issue = [&](int buf) {
        const unsigned b1 = buf ? (unsigned)S1_BUFB : 0u;
        const unsigned b2 = buf ? (unsigned)S2_BUFB : 0u;
        cp16(s1base + b1, base1, g1off[0]);                 // slot 0 (full)
        if (tid < S1_F4 - NTHREADS)                          // slot 1: tid < 96
            cp16(s1base + SLOT_B + b1, base1, g1off[1]);
        #pragma unroll
        for (int sl = 0; sl < 8; sl++) {
            const bool valid = (sl < 7) || (tid < S2_F4 - 7 * NTHREADS);  // sl7: tid<64
            if (valid) {
                unsigned dst = s2base + (unsigned)sl * SLOT_B + b2;
                if (pr[sl]) cp16(dst, base2, g2off[sl]);
                else        sts_zero16(dst);
            }
        }
        cp_commit();
    };

    float acc[9][6];
    #pragma unroll
    for (int j = 0; j < 9; j++)
        #pragma unroll
        for (int k = 0; k < 6; k++) acc[j][k] = 0.0f;

    unsigned t = blockIdx.x;
    setup(t);
    issue(0);
    unsigned gs = 0;

    const float scale = 0.08838834764831845f;   // 1/sqrt(128)

    for (;;) {
        unsigned q = t >> 1;
        unsigned obase = (((q >> 6) * 80u) * HH + ((q & 63u) * PH + pz)) * WW
                       + (t & 1u) * PW + 6 * tx;
        unsigned tnext = NTILES;

        #pragma unroll 1
        for (int st = 0; st < NSTAGES; st++, gs++) {
            const int bb = (int)(gs & 1u);
            cp_wait<0>();
            __syncthreads();

            if (st == 0) {
                if (tid == 0) s_next = atomicAdd(&g_ticket, 1u);
            }
            if (st < NSTAGES - 1) {
                g1off[0] += GSTEP; g1off[1] += GSTEP;
                #pragma unroll
                for (int sl = 0; sl < 8; sl++) g2off[sl] += GSTEP;
                issue(bb ^ 1);
            } else {
                tnext = s_next;                 // written at st==0; 15 syncs ago
                if (tnext < NTILES) { setup(tnext); issue(bb ^ 1); }
            }

            const float* q1 = &s1[bb][0][pz][6 * tx];
            const float* q2 = &s2[bb][0][r2][6 * tx];
            #pragma unroll
            for (int ch = 0; ch < CHS; ch++) {
                const float* c1 = q1 + ch * (PH * PW);
                const float* c2 = q2 + ch * (HALO_H * HALO_W);
                float2 a01 = *(const float2*)(c1);
                float2 a23 = *(const float2*)(c1 + 2);
                float2 a45 = *(const float2*)(c1 + 4);
                float2 v0  = *(const float2*)(c2);
                float2 v1  = *(const float2*)(c2 + 2);
                float2 v2  = *(const float2*)(c2 + 4);
                float2 v3  = *(const float2*)(c2 + 6);
                float2 v4  = *(const float2*)(c2 + 8);
                float2 v5  = *(const float2*)(c2 + 10);
                float2 v6  = *(const float2*)(c2 + 12);
                float a[6]  = {a01.x, a01.y, a23.x, a23.y, a45.x, a45.y};
                float v[14] = {v0.x, v0.y, v1.x, v1.y, v2.x, v2.y, v3.x, v3.y,
                               v4.x, v4.y, v5.x, v5.y, v6.x, v6.y};
                #pragma unroll
                for (int j = 0; j < 9; j++)
                    #pragma unroll
                    for (int k = 0; k < 6; k++)
                        acc[j][k] = fmaf(a[k], v[j + k], acc[j][k]);
            }
        }

        // ---- epilogue (overlaps the already-issued next-tile loads) ----
        #pragma unroll
        for (int j = 0; j < 9; j++) {
            int lin = diI * 9 + j;
            if (lin == 40) continue;               // (0,0) displacement
            int d = lin - (lin > 40 ? 1 : 0);
            float* dst = &out[obase + (unsigned)d * (HH * WW)];
            *(float2*)dst       = make_float2(acc[j][0] * scale, acc[j][1] * scale);
            *(float2*)(dst + 2) = make_float2(acc[j][2] * scale, acc[j][3] * scale);
            *(float2*)(dst + 4) = make_float2(acc[j][4] * scale, acc[j][5] * scale);
        }

        if (tnext >= NTILES) break;
        #pragma unroll
        for (int j = 0; j < 9; j++)
            #pragma unroll
            for (int k = 0; k < 6; k++) acc[j][k] = 0.0f;
        t = tnext;
    }
}

extern "C" void kernel_launch(void* const* d_in, const int* in_sizes, int n_in,
                              void* d_out, int out_size)
{
    const float* x1 = (const float*)d_in[0];
    const float* x2 = (const float*)d_in[1];
    float* out = (float*)d_out;

    reset_ticket<<<1, 1>>>();
    corr_kernel<<<NBLK, NTHREADS>>>(x1, x2, out);
}

// round 11
// speedup vs baseline: 1.0259x; 1.0026x over previous
#include <cuda_runtime.h>
#include <cuda_bf16.h>

// CorrelationLayer: out[b,d,h,w] = (1/sqrt(C)) * sum_c x1[b,c,h,w] * x2pad[b,c,h+di,w+dj]
// 80 displacements. B=8, C=128, H=128, W=192, fp32.
// v11: 6 px/thread core (R10) + DEPTH-4 cp.async pipeline (CHS=4, 4 buffers,
//      wait_group<2> -> 2 sub-stages of latency cover), persistent ticket
//      scheduler, continuous pipeline across tiles.

#define CC   128
#define HH   128
#define WW   192
#define PW   96
#define PH   2
#define CHS  4
#define TX   16
#define NTHREADS 288
#define NSTAGES  32
#define HALO_H   10
#define HALO_W   104
#define S1_FLT   (CHS * PH * PW)          // 768
#define S2_FLT   (CHS * HALO_H * HALO_W)  // 4160
#define S1_F4    (S1_FLT / 4)             // 192
#define S2_F4    (S2_FLT / 4)             // 1040
#define NBUF     4
#define NTILES   (2 * 64 * 8)             // 1024
#define NBLK     296                      // 148 SMs * 2 blocks
#define GSTEP    ((unsigned)(CHS * HH * WW * 4))   // 393216 B
#define S1_BUFB  (S1_FLT * 4)             // 3072 B
#define S2_BUFB  (S2_FLT * 4)             // 16640 B
#define SLOT_B   (NTHREADS * 16)          // 4608 B

__device__ unsigned g_ticket;
__global__ void reset_ticket() { g_ticket = NBLK; }

__device__ __forceinline__ unsigned smem_u32(const void* p) {
    return (unsigned)__cvta_generic_to_shared(p);
}
__device__ __forceinline__ void cp16(unsigned dst, const char* base, unsigned off) {
    asm volatile("cp.async.cg.shared.global [%0], [%1], 16;\n"
                 :: "r"(dst), "l"(base + off));
}
__device__ __forceinline__ void sts_zero16(unsigned dst) {
    asm volatile("st.shared.v4.u32 [%0], {%1,%1,%1,%1};\n" :: "r"(dst), "r"(0u));
}
__device__ __forceinline__ void cp_commit() {
    asm volatile("cp.async.commit_group;\n" ::: "memory");
}
template <int N> __device__ __forceinline__ void cp_wait() {
    asm volatile("cp.async.wait_group %0;\n" :: "n"(N) : "memory");
}

__global__ __launch_bounds__(NTHREADS, 2)
void corr_kernel(const float* __restrict__ x1,
                 const float* __restrict__ x2,
                 float* __restrict__ out)
{
    __shared__ __align__(16) float s1[NBUF][CHS][PH][PW];          // 12 KB
    __shared__ __align__(16) float s2[NBUF][CHS][HALO_H][HALO_W];  // 65 KB
    __shared__ unsigned s_next;

    const int tid = threadIdx.x;
    const int tx  = tid & 15;
    const int hs  = (tid >> 4) & 1;
    const int w   = tid >> 5;
    const int pz  = hs;                       // diagonal pairing
    const int diI = hs ? (w + 8) % 9 : w;
    const int r2  = pz + diI;

    const char* base1 = (const char*)x1;
    const char* base2 = (const char*)x2;

    // Affine smem slot addresses: slot f4 index i = tid + 288*sl -> byte 16*i.
    const unsigned s1base = smem_u32(&s1[0][0][0][0]) + 16u * tid;
    const unsigned s2base = smem_u32(&s2[0][0][0][0]) + 16u * tid;

    unsigned g1off;                // s1 slot (tid < 192)
    unsigned g2off[4];
    bool     pr[4];
    const bool h1 = (tid < S1_F4);

    auto setup = [&](unsigned t) {
        int w0 = (int)(t & 1u) * PW;
        unsigned q = t >> 1;
        int h0 = (int)(q & 63u) * PH;
        int b  = (int)(q >> 6);
        {
            int ii = h1 ? tid : 0;
            int ch = ii / 48, rem = ii - ch * 48;       // 48 f4/ch (2 rows x 24)
            int rr = rem / 24, c4 = rem - rr * 24;
            g1off = (unsigned)((((b * CC + ch) * HH + h0 + rr) * WW + w0 + 4 * c4) * 4);
        }
        #pragma unroll
        for (int sl = 0; sl < 4; sl++) {
            int i  = tid + NTHREADS * sl;
            int ii = (i < S2_F4) ? i : 0;
            int ch  = ii / 260, rem = ii - ch * 260;    // 260 f4/ch (10 x 26)
            int rr  = rem / 26,  c4 = rem - rr * 26;
            int hr  = h0 - 4 + rr;
            int wc  = w0 - 4 + 4 * c4;
            pr[sl] = (i < S2_F4) && (hr >= 0) && (hr < HH) && (wc >= 0) && (wc < WW);
            int hrc = pr[sl] ? hr : 0;
            int wcc = pr[sl] ? wc : 0;
            g2off[sl] = (unsigned)((((b * CC + ch) * HH + hrc) * WW + wcc) * 4);
        }
    };

    auto issue = [&](unsigned buf) {
        const unsigned b1 = buf * (unsigned)S1_BUFB;
        const unsigned b2 = buf * (unsigned)S2_BUFB;
        if (h1) cp16(s1base + b1, base1, g1off);
        #pragma unroll
        for (int sl = 0; sl < 4; sl++) {
            const bool valid = (sl < 3) || (tid < S2_F4 - 3 * NTHREADS);  // sl3: tid<176
            if (valid) {
                unsigned dst = s2base + (unsigned)sl * SLOT_B + b2;
                if (pr[sl]) cp16(dst, base2, g2off[sl]);
                else        sts_zero16(dst);
            }
        }
        cp_commit();
    };
    auto advance = [&]() {
        g1off += GSTEP;
        #pragma unroll
        for (int sl = 0; sl < 4; sl++) g2off[sl] += GSTEP;
    };

    float acc[9][6];
    #pragma unroll
    for (int j = 0; j < 9; j++)
        #pragma unroll
        for (int k = 0; k < 6; k++) acc[j][k] = 0.0f;

    unsigned t = blockIdx.x;
    setup(t);
    issue(0);                      // stage 0
    advance(); issue(1);           // stage 1
    advance(); issue(2);           // stage 2
    unsigned gs = 0;               // global sub-stage counter (buffer = gs & 3)

    const float scale = 0.08838834764831845f;   // 1/sqrt(128)

    for (;;) {
        unsigned q = t >> 1;
        unsigned obase = (((q >> 6) * 80u) * HH + ((q & 63u) * PH + pz)) * WW
                       + (t & 1u) * PW + 6 * tx;
        unsigned tnext = NTILES;

        #pragma unroll 1
        for (int st = 0; st < NSTAGES; st++, gs++) {
            // wait for sub-stage st; keep up to 2 younger groups in flight
            if (st == NSTAGES - 2 && tnext >= NTILES)      cp_wait<1>();
            else if (st == NSTAGES - 1 && tnext >= NTILES) cp_wait<0>();
            else                                           cp_wait<2>();
            __syncthreads();

            if (st == 0) {
                if (tid == 0) s_next = atomicAdd(&g_ticket, 1u);
            }
            // issue sub-stage st+3
            if (st < NSTAGES - 3) {
                advance();
                issue((gs + 3) & 3u);
            } else {
                // st+3 is next tile's sub-stage 0/1/2
                if (st == NSTAGES - 3) {
                    tnext = s_next;                      // written at st==0
                    if (tnext < NTILES) { setup(tnext); issue((gs + 3) & 3u); }
                } else if (tnext < NTILES) {
                    advance();
                    issue((gs + 3) & 3u);
                }
            }

            const unsigned buf = gs & 3u;
            const float* q1 = &s1[buf][0][pz][6 * tx];
            const float* q2 = &s2[buf][0][r2][6 * tx];
            #pragma unroll
            for (int ch = 0; ch < CHS; ch++) {
                const float* c1 = q1 + ch * (PH * PW);
                const float* c2 = q2 + ch * (HALO_H * HALO_W);
                float2 a01 = *(const float2*)(c1);
                float2 a23 = *(const float2*)(c1 + 2);
                float2 a45 = *(const float2*)(c1 + 4);
                float2 v0  = *(const float2*)(c2);
                float2 v1  = *(const float2*)(c2 + 2);
                float2 v2  = *(const float2*)(c2 + 4);
                float2 v3  = *(const float2*)(c2 + 6);
                float2 v4  = *(const float2*)(c2 + 8);
                float2 v5  = *(const float2*)(c2 + 10);
                float2 v6  = *(const float2*)(c2 + 12);
                float a[6]  = {a01.x, a01.y, a23.x, a23.y, a45.x, a45.y};
                float v[14] = {v0.x, v0.y, v1.x, v1.y, v2.x, v2.y, v3.x, v3.y,
                               v4.x, v4.y, v5.x, v5.y, v6.x, v6.y};
                #pragma unroll
                for (int j = 0; j < 9; j++)
                    #pragma unroll
                    for (int k = 0; k < 6; k++)
                        acc[j][k] = fmaf(a[k], v[j + k], acc[j][k]);
            }
        }

        // ---- epilogue (overlaps in-flight next-tile loads) ----
        #pragma unroll
        for (int j = 0; j < 9; j++) {
            int lin = diI * 9 + j;
            if (lin == 40) continue;               // (0,0) displacement
            int d = lin - (lin > 40 ? 1 : 0);
            float* dst = &out[obase + (unsigned)d * (HH * WW)];
            *(float2*)dst       = make_float2(acc[j][0] * scale, acc[j][1] * scale);
            *(float2*)(dst + 2) = make_float2(acc[j][2] * scale, acc[j][3] * scale);
            *(float2*)(dst + 4) = make_float2(acc[j][4] * scale, acc[j][5] * scale);
        }

        if (tnext >= NTILES) break;
        #pragma unroll
        for (int j = 0; j < 9; j++)
            #pragma unroll
            for (int k = 0; k < 6; k++) acc[j][k] = 0.0f;
        t = tnext;
    }
}

extern "C" void kernel_launch(void* const* d_in, const int* in_sizes, int n_in,
                              void* d_out, int out_size)
{
    const float* x1 = (const float*)d_in[0];
    const float* x2 = (const float*)d_in[1];
    float* out = (float*)d_out;

    reset_ticket<<<1, 1>>>();
    corr_kernel<<<NBLK, NTHREADS>>>(x1, x2, out);
}